// round 1
// baseline (speedup 1.0000x reference)
#include <cuda_runtime.h>
#include <cuda_bf16.h>
#include <cstdint>

// ---------------- problem constants ----------------
constexpr int CB   = 2;      // batch
constexpr int CK   = 4;      // RVQ codebooks / heads
constexpr int CT   = 1024;   // sequence length
constexpr int CV   = 1024;   // vocab
constexpr int CDM  = 512;    // d_model
constexpr int CDI  = 1024;   // d_inner
constexpr int CNS  = 16;     // state size N
constexpr int CDC  = 4;      // conv width
constexpr int CDTR = 32;     // dt rank
constexpr int CL   = 2;      // layers
constexpr int CCH  = 64;     // scan chunks
constexpr int CCL  = 16;     // chunk length (CCH*CCL == CT)
constexpr int XD   = CDTR + 2 * CNS;   // 64 (x_dbl width)
constexpr int KSPLIT = 8;    // split-K factor for x_proj GEMM

// ---------------- scratch (static device memory; no allocation allowed) ----
__device__ float g_x   [CB * CT * CDM];          // residual stream
__device__ float g_xn  [CB * CT * CDM];          // rmsnormed
__device__ float g_xz  [CB * CT * 2 * CDI];      // in_proj output (x | z)
__device__ float g_xssm[CB * CT * CDI];          // conv+silu output
__device__ float g_xdbl[CB * CT * XD];           // x_proj output
__device__ float g_xdpart[KSPLIT * CB * CT * XD];// split-K partials
__device__ float g_dt  [CB * CT * CDI];          // softplus(dt)
__device__ float g_y   [CB * CT * CDI];          // gated scan output
__device__ float g_hend  [CB * CDI * CCH * CNS];
__device__ float g_prod  [CB * CDI * CCH * CNS];
__device__ float g_hstart[CB * CDI * CCH * CNS];

// ---------------- small math helpers ----------------
__device__ __forceinline__ float siluf(float x) {
    return x / (1.0f + __expf(-x));
}
__device__ __forceinline__ float softplusf(float x) {
    return fmaxf(x, 0.0f) + log1pf(__expf(-fabsf(x)));
}

// ---------------- embedding: x[b,t,d] = sum_k E[k, codes[b,k,t], d] --------
__global__ void embed_kernel(const int* __restrict__ codes,
                             const float* __restrict__ ew,
                             float* __restrict__ xout) {
    int idx = blockIdx.x * blockDim.x + threadIdx.x;   // over CB*CT*CDM
    int d  = idx & (CDM - 1);
    int bt = idx / CDM;
    int t  = bt & (CT - 1);
    int b  = bt / CT;
    float s = 0.0f;
#pragma unroll
    for (int k = 0; k < CK; k++) {
        int code = codes[(b * CK + k) * CT + t];
        s += ew[((size_t)k * CV + code) * CDM + d];
    }
    xout[idx] = s;
}

// ---------------- rmsnorm (one block per token, 256 threads, 2 elem/thr) ---
__global__ void rmsnorm_kernel(const float* __restrict__ x,
                               const float* __restrict__ w,
                               float* __restrict__ out) {
    int tok = blockIdx.x;                // 0..CB*CT-1
    int tid = threadIdx.x;               // 0..255
    const float* xr = x + (size_t)tok * CDM;
    float v0 = xr[tid], v1 = xr[tid + 256];
    float ss = v0 * v0 + v1 * v1;
#pragma unroll
    for (int off = 16; off; off >>= 1) ss += __shfl_xor_sync(0xffffffffu, ss, off);
    __shared__ float red[8];
    if ((tid & 31) == 0) red[tid >> 5] = ss;
    __syncthreads();
    float tot = 0.0f;
#pragma unroll
    for (int i = 0; i < 8; i++) tot += red[i];
    float r = rsqrtf(tot * (1.0f / CDM) + 1e-6f);
    float* orow = out + (size_t)tok * CDM;
    orow[tid]       = v0 * w[tid] * r;
    orow[tid + 256] = v1 * w[tid + 256] * r;
}

// ---------------- generic tiled SGEMM ------------------------------------
// C[m,n] = epi( sum_k A[m,k] * B(n,k) )   (NT: B row-major N x K; NN: K x N)
// EPI: 0 = plain store, 1 = softplus(acc + bias[n]), 2 = acc + res[m*ldc+n]
// ZMODE: 0 = none, 1 = split-K via blockIdx.z (partials), 2 = batched head
template<int BM, int BN, int BK, int TM, int TN, int EPI, bool NT, int ZMODE>
__global__ __launch_bounds__((BM / TM) * (BN / TN))
void sgemm_kernel(const float* __restrict__ A, const float* __restrict__ B,
                  float* __restrict__ C, int M, int N, int Kt,
                  int lda, int ldb, int ldc,
                  const float* __restrict__ bias, const float* __restrict__ res,
                  int nsplit) {
    constexpr int THREADS = (BM / TM) * (BN / TN);
    __shared__ float As[BK][BM];
    __shared__ float Bs[BK][BN];
    int tid = threadIdx.x;
    int bn = blockIdx.x * BN, bm = blockIdx.y * BM;
    int k_begin = 0, k_end = Kt;
    if (ZMODE == 1) {
        int ks = Kt / nsplit;
        k_begin = blockIdx.z * ks;
        k_end   = k_begin + ks;
        C += (size_t)blockIdx.z * M * ldc;
    }
    if (ZMODE == 2) {   // head: z = b*CK + k
        int zb = blockIdx.z >> 2, zk = blockIdx.z & 3;
        A += (size_t)zb * CT * CDM;
        B += (size_t)zk * CDM * CV;
        C += (size_t)blockIdx.z * CT * CV;
    }
    constexpr int BNT = BN / TN;
    int tc = tid % BNT, tr = tid / BNT;
    float acc[TM][TN];
#pragma unroll
    for (int i = 0; i < TM; i++)
#pragma unroll
        for (int j = 0; j < TN; j++) acc[i][j] = 0.0f;

    for (int kb = k_begin; kb < k_end; kb += BK) {
        // load A tile (BM x BK), transpose to As[k][m]
#pragma unroll
        for (int i = tid * 4; i < BM * BK; i += THREADS * 4) {
            int r = i / BK, c = i % BK;
            float4 v = *reinterpret_cast<const float4*>(A + (size_t)(bm + r) * lda + kb + c);
            As[c + 0][r] = v.x; As[c + 1][r] = v.y;
            As[c + 2][r] = v.z; As[c + 3][r] = v.w;
        }
        if (NT) {
#pragma unroll
            for (int i = tid * 4; i < BN * BK; i += THREADS * 4) {
                int r = i / BK, c = i % BK;
                float4 v = make_float4(0.f, 0.f, 0.f, 0.f);
                if (bn + r < N)
                    v = *reinterpret_cast<const float4*>(B + (size_t)(bn + r) * ldb + kb + c);
                Bs[c + 0][r] = v.x; Bs[c + 1][r] = v.y;
                Bs[c + 2][r] = v.z; Bs[c + 3][r] = v.w;
            }
        } else {
#pragma unroll
            for (int i = tid * 4; i < BK * BN; i += THREADS * 4) {
                int r = i / BN, c = i % BN;
                float4 v = *reinterpret_cast<const float4*>(B + (size_t)(kb + r) * ldb + bn + c);
                *reinterpret_cast<float4*>(&Bs[r][c]) = v;
            }
        }
        __syncthreads();
#pragma unroll
        for (int kk = 0; kk < BK; kk++) {
            float a[TM], bf[TN];
#pragma unroll
            for (int i = 0; i < TM; i++) a[i] = As[kk][tr * TM + i];
#pragma unroll
            for (int j = 0; j < TN; j++) bf[j] = Bs[kk][tc * TN + j];
#pragma unroll
            for (int i = 0; i < TM; i++)
#pragma unroll
                for (int j = 0; j < TN; j++) acc[i][j] = fmaf(a[i], bf[j], acc[i][j]);
        }
        __syncthreads();
    }
#pragma unroll
    for (int i = 0; i < TM; i++) {
        int m = bm + tr * TM + i;
#pragma unroll
        for (int j = 0; j < TN; j++) {
            int n = bn + tc * TN + j;
            if (n < N) {
                float v = acc[i][j];
                if (EPI == 1) { v += bias[n]; v = softplusf(v); }
                if (EPI == 2) { v += res[(size_t)m * ldc + n]; }
                C[(size_t)m * ldc + n] = v;
            }
        }
    }
}

// ---------------- split-K reduction for x_proj ---------------------------
__global__ void reduce_xdbl_kernel() {
    int idx = blockIdx.x * blockDim.x + threadIdx.x;  // over CB*CT*XD
    float s = 0.0f;
#pragma unroll
    for (int z = 0; z < KSPLIT; z++) s += g_xdpart[(size_t)z * CB * CT * XD + idx];
    g_xdbl[idx] = s;
}

// ---------------- causal depthwise conv (width 4) + SiLU ------------------
__global__ void conv_silu_kernel(const float* __restrict__ xz,
                                 const float* __restrict__ cw,
                                 const float* __restrict__ cb) {
    int idx = blockIdx.x * blockDim.x + threadIdx.x;   // over CB*CT*CDI
    int d = idx & (CDI - 1);
    int bt = idx / CDI;
    int t = bt & (CT - 1);
    int b = bt / CT;
    const float* w = cw + d * CDC;
    float acc = cb[d];
#pragma unroll
    for (int j = 0; j < CDC; j++) {
        int tt = t - (CDC - 1) + j;
        if (tt >= 0) acc += w[j] * xz[((size_t)(b * CT + tt)) * (2 * CDI) + d];
    }
    g_xssm[idx] = siluf(acc);
}

// ---------------- selective scan: pass A (per-chunk local scan) ------------
__global__ void scan_passA_kernel(const float* __restrict__ A_log) {
    int d = blockIdx.x * blockDim.x + threadIdx.x;   // 0..CDI-1
    int chunk = blockIdx.y;
    int b = blockIdx.z;
    float Ar[CNS], h[CNS], P[CNS];
#pragma unroll
    for (int n = 0; n < CNS; n++) {
        Ar[n] = -__expf(A_log[d * CNS + n]);
        h[n] = 0.0f;
        P[n] = 1.0f;
    }
    int t0 = chunk * CCL;
#pragma unroll 4
    for (int j = 0; j < CCL; j++) {
        int t = t0 + j;
        size_t row = (size_t)(b * CT + t);
        float dtv = g_dt[row * CDI + d];
        float xv  = g_xssm[row * CDI + d];
        float dtx = dtv * xv;
        const float* bp = g_xdbl + row * XD + CDTR;
#pragma unroll
        for (int n = 0; n < CNS; n++) {
            float dA = __expf(dtv * Ar[n]);
            h[n] = fmaf(dA, h[n], dtx * bp[n]);
            P[n] *= dA;
        }
    }
    size_t base = (((size_t)(b * CDI + d)) * CCH + chunk) * CNS;
#pragma unroll
    for (int n = 0; n < CNS; n++) { g_hend[base + n] = h[n]; g_prod[base + n] = P[n]; }
}

// ---------------- scan: sequential chunk combine ---------------------------
__global__ void scan_combine_kernel() {
    int idx = blockIdx.x * blockDim.x + threadIdx.x;  // over CB*CDI*CNS
    int n = idx & (CNS - 1);
    int bd = idx / CNS;
    size_t base = (size_t)bd * CCH * CNS + n;
    float H = 0.0f;
#pragma unroll 8
    for (int c = 0; c < CCH; c++) {
        g_hstart[base + (size_t)c * CNS] = H;
        H = fmaf(g_prod[base + (size_t)c * CNS], H, g_hend[base + (size_t)c * CNS]);
    }
}

// -------- scan: pass B (replay with true init; fused D-skip + SiLU gate) ---
__global__ void scan_passB_kernel(const float* __restrict__ A_log,
                                  const float* __restrict__ Dskip) {
    int d = blockIdx.x * blockDim.x + threadIdx.x;
    int chunk = blockIdx.y;
    int b = blockIdx.z;
    float Ar[CNS], h[CNS];
    size_t hbase = (((size_t)(b * CDI + d)) * CCH + chunk) * CNS;
#pragma unroll
    for (int n = 0; n < CNS; n++) {
        Ar[n] = -__expf(A_log[d * CNS + n]);
        h[n] = g_hstart[hbase + n];
    }
    float dsk = Dskip[d];
    int t0 = chunk * CCL;
#pragma unroll 4
    for (int j = 0; j < CCL; j++) {
        int t = t0 + j;
        size_t row = (size_t)(b * CT + t);
        float dtv = g_dt[row * CDI + d];
        float xv  = g_xssm[row * CDI + d];
        float dtx = dtv * xv;
        const float* bp = g_xdbl + row * XD + CDTR;
        const float* cp = bp + CNS;
        float y = 0.0f;
#pragma unroll
        for (int n = 0; n < CNS; n++) {
            float dA = __expf(dtv * Ar[n]);
            h[n] = fmaf(dA, h[n], dtx * bp[n]);
            y = fmaf(h[n], cp[n], y);
        }
        float zv = g_xz[row * (2 * CDI) + CDI + d];
        g_y[row * CDI + d] = (y + xv * dsk) * siluf(zv);
    }
}

// ---------------- host-side launcher ---------------------------------------
extern "C" void kernel_launch(void* const* d_in, const int* in_sizes, int n_in,
                              void* d_out, int out_size) {
    const int*   codes     = (const int*)d_in[0];
    const float* embed_w   = (const float*)d_in[1];
    const float* norm_w    = (const float*)d_in[2];
    const float* in_proj_w = (const float*)d_in[3];
    const float* conv_w    = (const float*)d_in[4];
    const float* conv_b    = (const float*)d_in[5];
    const float* x_proj_w  = (const float*)d_in[6];
    const float* dt_proj_w = (const float*)d_in[7];
    const float* dt_proj_b = (const float*)d_in[8];
    const float* A_log     = (const float*)d_in[9];
    const float* D_skip    = (const float*)d_in[10];
    const float* out_proj_w= (const float*)d_in[11];
    const float* head_w    = (const float*)d_in[12];
    float* out = (float*)d_out;

    float *px, *pxn, *pxz, *pxssm, *pxdpart, *pdt, *py;
    cudaGetSymbolAddress((void**)&px, g_x);
    cudaGetSymbolAddress((void**)&pxn, g_xn);
    cudaGetSymbolAddress((void**)&pxz, g_xz);
    cudaGetSymbolAddress((void**)&pxssm, g_xssm);
    cudaGetSymbolAddress((void**)&pxdpart, g_xdpart);
    cudaGetSymbolAddress((void**)&pdt, g_dt);
    cudaGetSymbolAddress((void**)&py, g_y);
    float* pxdbl; cudaGetSymbolAddress((void**)&pxdbl, g_xdbl);

    const int M = CB * CT;   // 2048 tokens

    // 1) RVQ sum-embedding
    embed_kernel<<<(CB * CT * CDM) / 256, 256>>>(codes, embed_w, px);

    for (int l = 0; l < CL; l++) {
        const float* nw  = norm_w    + (size_t)l * CDM;
        const float* iw  = in_proj_w + (size_t)l * 2 * CDI * CDM;
        const float* cw  = conv_w    + (size_t)l * CDI * CDC;
        const float* cb  = conv_b    + (size_t)l * CDI;
        const float* xpw = x_proj_w  + (size_t)l * XD * CDI;
        const float* dpw = dt_proj_w + (size_t)l * CDI * CDTR;
        const float* dpb = dt_proj_b + (size_t)l * CDI;
        const float* al  = A_log     + (size_t)l * CDI * CNS;
        const float* ds  = D_skip    + (size_t)l * CDI;
        const float* ow  = out_proj_w+ (size_t)l * CDM * CDI;

        // rmsnorm
        rmsnorm_kernel<<<M, 256>>>(px, nw, pxn);

        // in_proj: (2048 x 512) @ (2048 x 512)^T -> 2048 x 2048
        sgemm_kernel<128, 128, 8, 8, 8, 0, true, 0>
            <<<dim3(2 * CDI / 128, M / 128, 1), 256>>>(
                pxn, iw, pxz, M, 2 * CDI, CDM, CDM, CDM, 2 * CDI, nullptr, nullptr, 1);

        // causal dwconv + silu
        conv_silu_kernel<<<(CB * CT * CDI) / 256, 256>>>(pxz, cw, cb);

        // x_proj (skinny): split-K=8 -> partials, then reduce
        sgemm_kernel<64, 64, 8, 4, 4, 0, true, 1>
            <<<dim3(1, M / 64, KSPLIT), 256>>>(
                pxssm, xpw, pxdpart, M, XD, CDI, CDI, CDI, XD, nullptr, nullptr, KSPLIT);
        reduce_xdbl_kernel<<<(CB * CT * XD) / 256, 256>>>();

        // dt = softplus(dt_lr @ dtp_w^T + b):  (2048 x 32) @ (1024 x 32)^T
        sgemm_kernel<64, 64, 8, 4, 4, 1, true, 0>
            <<<dim3(CDI / 64, M / 64, 1), 256>>>(
                pxdbl, dpw, pdt, M, CDI, CDTR, XD, CDTR, CDI, dpb, nullptr, 1);

        // chunked parallel selective scan
        scan_passA_kernel<<<dim3(CDI / 256, CCH, CB), 256>>>(al);
        scan_combine_kernel<<<(CB * CDI * CNS) / 256, 256>>>();
        scan_passB_kernel<<<dim3(CDI / 256, CCH, CB), 256>>>(al, ds);

        // out_proj + residual: x = x + y @ ow^T
        sgemm_kernel<64, 64, 8, 4, 4, 2, true, 0>
            <<<dim3(CDM / 64, M / 64, 1), 256>>>(
                py, ow, px, M, CDM, CDI, CDI, CDI, CDM, nullptr, px, 1);
    }

    // head: out[b,k,t,v] = x[b,t,:] @ head_w[k]   (NN, batched over z=b*K+k)
    sgemm_kernel<128, 128, 8, 8, 8, 0, false, 2>
        <<<dim3(CV / 128, CT / 128, CB * CK), 256>>>(
            px, head_w, out, CT, CV, CDM, CDM, CV, CV, nullptr, nullptr, 1);

    (void)in_sizes; (void)n_in; (void)out_size;
}

// round 2
// speedup vs baseline: 1.5901x; 1.5901x over previous
#include <cuda_runtime.h>
#include <cuda_bf16.h>
#include <cstdint>

// ---------------- problem constants ----------------
constexpr int CB   = 2;      // batch
constexpr int CK   = 4;      // RVQ codebooks / heads
constexpr int CT   = 1024;   // sequence length
constexpr int CV   = 1024;   // vocab
constexpr int CDM  = 512;    // d_model
constexpr int CDI  = 1024;   // d_inner
constexpr int CNS  = 16;     // state size N
constexpr int CDC  = 4;      // conv width
constexpr int CDTR = 32;     // dt rank
constexpr int CL   = 2;      // layers
constexpr int CCH  = 64;     // scan chunks
constexpr int CCL  = 16;     // chunk length (CCH*CCL == CT)
constexpr int XD   = CDTR + 2 * CNS;   // 64 (x_dbl width)
constexpr int KSPLIT = 8;    // split-K factor for x_proj GEMM

// ---------------- scratch (static device memory; no allocation allowed) ----
__device__ float g_x   [CB * CT * CDM];          // residual stream
__device__ float g_xn  [CB * CT * CDM];          // rmsnormed
__device__ float g_xz  [CB * CT * 2 * CDI];      // in_proj output (x | z)
__device__ float g_xssm[CB * CT * CDI];          // conv+silu output
__device__ float g_xdbl[CB * CT * XD];           // x_proj output
__device__ float g_xdpart[KSPLIT * CB * CT * XD];// split-K partials
__device__ float g_dt  [CB * CT * CDI];          // softplus(dt)
__device__ float g_y   [CB * CT * CDI];          // gated scan output
__device__ float g_hend  [CB * CDI * CCH * CNS];
__device__ float g_prod  [CB * CDI * CCH * CNS];
__device__ float g_hstart[CB * CDI * CCH * CNS];

// ---------------- small math helpers ----------------
__device__ __forceinline__ float siluf(float x) {
    return x / (1.0f + __expf(-x));
}
__device__ __forceinline__ float softplusf(float x) {
    return fmaxf(x, 0.0f) + log1pf(__expf(-fabsf(x)));
}
__device__ __forceinline__ uint32_t f2tf32(float f) {
    uint32_t r; asm("cvt.rna.tf32.f32 %0, %1;" : "=r"(r) : "f"(f)); return r;
}

// ---------------- embedding: x[b,t,d] = sum_k E[k, codes[b,k,t], d] --------
__global__ void embed_kernel(const int* __restrict__ codes,
                             const float* __restrict__ ew,
                             float* __restrict__ xout) {
    int idx = blockIdx.x * blockDim.x + threadIdx.x;   // over CB*CT*CDM
    int d  = idx & (CDM - 1);
    int bt = idx / CDM;
    int t  = bt & (CT - 1);
    int b  = bt / CT;
    float s = 0.0f;
#pragma unroll
    for (int k = 0; k < CK; k++) {
        int code = codes[(b * CK + k) * CT + t];
        s += ew[((size_t)k * CV + code) * CDM + d];
    }
    xout[idx] = s;
}

// ---------------- rmsnorm (one block per token, 256 threads, 2 elem/thr) ---
__global__ void rmsnorm_kernel(const float* __restrict__ x,
                               const float* __restrict__ w,
                               float* __restrict__ out) {
    int tok = blockIdx.x;                // 0..CB*CT-1
    int tid = threadIdx.x;               // 0..255
    const float* xr = x + (size_t)tok * CDM;
    float v0 = xr[tid], v1 = xr[tid + 256];
    float ss = v0 * v0 + v1 * v1;
#pragma unroll
    for (int off = 16; off; off >>= 1) ss += __shfl_xor_sync(0xffffffffu, ss, off);
    __shared__ float red[8];
    if ((tid & 31) == 0) red[tid >> 5] = ss;
    __syncthreads();
    float tot = 0.0f;
#pragma unroll
    for (int i = 0; i < 8; i++) tot += red[i];
    float r = rsqrtf(tot * (1.0f / CDM) + 1e-6f);
    float* orow = out + (size_t)tok * CDM;
    orow[tid]       = v0 * w[tid] * r;
    orow[tid + 256] = v1 * w[tid + 256] * r;
}

// ====================================================================
// TF32 tensor-core GEMM via mma.sync.m16n8k8 (fp32 accumulate)
// C[m,n] = epi( sum_k A[m,k] * B(n,k) )
// NT: B is row-major N x K (weights). !NT: B is row-major K x N.
// EPI: 0 plain, 2 residual add (res[m*ldc+n]).
// ZMODE 2: batched head, z = b*CK + k.
// Block 128x128x16, 8 warps, warp tile 32x64.
// ====================================================================
template<int EPI, bool NT, int ZMODE>
__global__ __launch_bounds__(256)
void mma_gemm_kernel(const float* __restrict__ A, const float* __restrict__ B,
                     float* __restrict__ C, int M, int N, int K,
                     int lda, int ldb, int ldc, const float* __restrict__ res) {
    constexpr int BM = 128, BN = 128, BK = 16;
    constexpr int LDSW = 136;   // word stride; 136 % 32 == 8 -> conflict-free frags
    __shared__ uint32_t As[BK][LDSW];
    __shared__ uint32_t Bs[BK][LDSW];

    int tid  = threadIdx.x;
    int warp = tid >> 5, lane = tid & 31;
    int q = lane & 3, g = lane >> 2;       // tid_in_group, groupID
    int wm = (warp >> 1) * 32;             // warp row offset in block tile
    int wn = (warp & 1) * 64;              // warp col offset
    int bm = blockIdx.y * BM, bn = blockIdx.x * BN;

    if (ZMODE == 2) {   // head: z = b*CK + k
        int zb = blockIdx.z >> 2, zk = blockIdx.z & 3;
        A += (size_t)zb * CT * CDM;
        B += (size_t)zk * CDM * CV;
        C += (size_t)blockIdx.z * CT * CV;
    }

    float c[2][8][4];
#pragma unroll
    for (int mi = 0; mi < 2; mi++)
#pragma unroll
        for (int ni = 0; ni < 8; ni++)
#pragma unroll
            for (int j = 0; j < 4; j++) c[mi][ni][j] = 0.0f;

    for (int kb = 0; kb < K; kb += BK) {
        // ---- A tile (BM x BK) -> As[k][m], tf32-converted ----
#pragma unroll
        for (int i = tid * 4; i < BM * BK; i += 1024) {
            int r = i >> 4, cc = i & 15;
            float4 v = *reinterpret_cast<const float4*>(A + (size_t)(bm + r) * lda + kb + cc);
            As[cc + 0][r] = f2tf32(v.x); As[cc + 1][r] = f2tf32(v.y);
            As[cc + 2][r] = f2tf32(v.z); As[cc + 3][r] = f2tf32(v.w);
        }
        // ---- B tile -> Bs[k][n], tf32-converted ----
        if (NT) {
#pragma unroll
            for (int i = tid * 4; i < BN * BK; i += 1024) {
                int r = i >> 4, cc = i & 15;
                float4 v = *reinterpret_cast<const float4*>(B + (size_t)(bn + r) * ldb + kb + cc);
                Bs[cc + 0][r] = f2tf32(v.x); Bs[cc + 1][r] = f2tf32(v.y);
                Bs[cc + 2][r] = f2tf32(v.z); Bs[cc + 3][r] = f2tf32(v.w);
            }
        } else {
#pragma unroll
            for (int i = tid * 4; i < BK * BN; i += 1024) {
                int r = i >> 7, cc = i & 127;
                float4 v = *reinterpret_cast<const float4*>(B + (size_t)(kb + r) * ldb + bn + cc);
                Bs[r][cc + 0] = f2tf32(v.x); Bs[r][cc + 1] = f2tf32(v.y);
                Bs[r][cc + 2] = f2tf32(v.z); Bs[r][cc + 3] = f2tf32(v.w);
            }
        }
        __syncthreads();

#pragma unroll
        for (int kk = 0; kk < BK; kk += 8) {
            int k0 = kk + q;
            uint32_t af[2][4], bf[8][2];
#pragma unroll
            for (int mi = 0; mi < 2; mi++) {
                int m = wm + mi * 16 + g;
                af[mi][0] = As[k0][m];     af[mi][1] = As[k0][m + 8];
                af[mi][2] = As[k0 + 4][m]; af[mi][3] = As[k0 + 4][m + 8];
            }
#pragma unroll
            for (int ni = 0; ni < 8; ni++) {
                int n = wn + ni * 8 + g;
                bf[ni][0] = Bs[k0][n]; bf[ni][1] = Bs[k0 + 4][n];
            }
#pragma unroll
            for (int mi = 0; mi < 2; mi++)
#pragma unroll
                for (int ni = 0; ni < 8; ni++) {
                    asm volatile(
                        "mma.sync.aligned.m16n8k8.row.col.f32.tf32.tf32.f32 "
                        "{%0,%1,%2,%3}, {%4,%5,%6,%7}, {%8,%9}, {%0,%1,%2,%3};"
                        : "+f"(c[mi][ni][0]), "+f"(c[mi][ni][1]),
                          "+f"(c[mi][ni][2]), "+f"(c[mi][ni][3])
                        : "r"(af[mi][0]), "r"(af[mi][1]), "r"(af[mi][2]), "r"(af[mi][3]),
                          "r"(bf[ni][0]), "r"(bf[ni][1]));
                }
        }
        __syncthreads();
    }

    // ---- epilogue ----
#pragma unroll
    for (int mi = 0; mi < 2; mi++) {
        int m0 = bm + wm + mi * 16 + g;
#pragma unroll
        for (int ni = 0; ni < 8; ni++) {
            int n0 = bn + wn + ni * 8 + q * 2;
            float2 v0 = make_float2(c[mi][ni][0], c[mi][ni][1]);
            float2 v1 = make_float2(c[mi][ni][2], c[mi][ni][3]);
            if (EPI == 2) {
                const float* r0 = res + (size_t)m0 * ldc + n0;
                const float* r1 = res + (size_t)(m0 + 8) * ldc + n0;
                v0.x += r0[0]; v0.y += r0[1];
                v1.x += r1[0]; v1.y += r1[1];
            }
            *reinterpret_cast<float2*>(C + (size_t)m0 * ldc + n0)       = v0;
            *reinterpret_cast<float2*>(C + (size_t)(m0 + 8) * ldc + n0) = v1;
        }
    }
}

// ---------------- generic tiled fp32 SGEMM (skinny GEMMs) ------------------
template<int BM, int BN, int BK, int TM, int TN, int EPI, bool NT, int ZMODE>
__global__ __launch_bounds__((BM / TM) * (BN / TN))
void sgemm_kernel(const float* __restrict__ A, const float* __restrict__ B,
                  float* __restrict__ C, int M, int N, int Kt,
                  int lda, int ldb, int ldc,
                  const float* __restrict__ bias, const float* __restrict__ res,
                  int nsplit) {
    constexpr int THREADS = (BM / TM) * (BN / TN);
    __shared__ float As[BK][BM];
    __shared__ float Bs[BK][BN];
    int tid = threadIdx.x;
    int bn = blockIdx.x * BN, bm = blockIdx.y * BM;
    int k_begin = 0, k_end = Kt;
    if (ZMODE == 1) {
        int ks = Kt / nsplit;
        k_begin = blockIdx.z * ks;
        k_end   = k_begin + ks;
        C += (size_t)blockIdx.z * M * ldc;
    }
    constexpr int BNT = BN / TN;
    int tc = tid % BNT, tr = tid / BNT;
    float acc[TM][TN];
#pragma unroll
    for (int i = 0; i < TM; i++)
#pragma unroll
        for (int j = 0; j < TN; j++) acc[i][j] = 0.0f;

    for (int kb = k_begin; kb < k_end; kb += BK) {
#pragma unroll
        for (int i = tid * 4; i < BM * BK; i += THREADS * 4) {
            int r = i / BK, c = i % BK;
            float4 v = *reinterpret_cast<const float4*>(A + (size_t)(bm + r) * lda + kb + c);
            As[c + 0][r] = v.x; As[c + 1][r] = v.y;
            As[c + 2][r] = v.z; As[c + 3][r] = v.w;
        }
        if (NT) {
#pragma unroll
            for (int i = tid * 4; i < BN * BK; i += THREADS * 4) {
                int r = i / BK, c = i % BK;
                float4 v = make_float4(0.f, 0.f, 0.f, 0.f);
                if (bn + r < N)
                    v = *reinterpret_cast<const float4*>(B + (size_t)(bn + r) * ldb + kb + c);
                Bs[c + 0][r] = v.x; Bs[c + 1][r] = v.y;
                Bs[c + 2][r] = v.z; Bs[c + 3][r] = v.w;
            }
        } else {
#pragma unroll
            for (int i = tid * 4; i < BK * BN; i += THREADS * 4) {
                int r = i / BN, c = i % BN;
                float4 v = *reinterpret_cast<const float4*>(B + (size_t)(kb + r) * ldb + bn + c);
                *reinterpret_cast<float4*>(&Bs[r][c]) = v;
            }
        }
        __syncthreads();
#pragma unroll
        for (int kk = 0; kk < BK; kk++) {
            float a[TM], bf[TN];
#pragma unroll
            for (int i = 0; i < TM; i++) a[i] = As[kk][tr * TM + i];
#pragma unroll
            for (int j = 0; j < TN; j++) bf[j] = Bs[kk][tc * TN + j];
#pragma unroll
            for (int i = 0; i < TM; i++)
#pragma unroll
                for (int j = 0; j < TN; j++) acc[i][j] = fmaf(a[i], bf[j], acc[i][j]);
        }
        __syncthreads();
    }
#pragma unroll
    for (int i = 0; i < TM; i++) {
        int m = bm + tr * TM + i;
#pragma unroll
        for (int j = 0; j < TN; j++) {
            int n = bn + tc * TN + j;
            if (n < N) {
                float v = acc[i][j];
                if (EPI == 1) { v += bias[n]; v = softplusf(v); }
                if (EPI == 2) { v += res[(size_t)m * ldc + n]; }
                C[(size_t)m * ldc + n] = v;
            }
        }
    }
}

// ---------------- split-K reduction for x_proj ---------------------------
__global__ void reduce_xdbl_kernel() {
    int idx = blockIdx.x * blockDim.x + threadIdx.x;  // over CB*CT*XD
    float s = 0.0f;
#pragma unroll
    for (int z = 0; z < KSPLIT; z++) s += g_xdpart[(size_t)z * CB * CT * XD + idx];
    g_xdbl[idx] = s;
}

// ---------------- causal depthwise conv (width 4) + SiLU ------------------
__global__ void conv_silu_kernel(const float* __restrict__ xz,
                                 const float* __restrict__ cw,
                                 const float* __restrict__ cb) {
    int idx = blockIdx.x * blockDim.x + threadIdx.x;   // over CB*CT*CDI
    int d = idx & (CDI - 1);
    int bt = idx / CDI;
    int t = bt & (CT - 1);
    int b = bt / CT;
    const float* w = cw + d * CDC;
    float acc = cb[d];
#pragma unroll
    for (int j = 0; j < CDC; j++) {
        int tt = t - (CDC - 1) + j;
        if (tt >= 0) acc += w[j] * xz[((size_t)(b * CT + tt)) * (2 * CDI) + d];
    }
    g_xssm[idx] = siluf(acc);
}

// ---------------- selective scan: pass A (per-chunk local scan) ------------
__global__ void scan_passA_kernel(const float* __restrict__ A_log) {
    int d = blockIdx.x * blockDim.x + threadIdx.x;   // 0..CDI-1
    int chunk = blockIdx.y;
    int b = blockIdx.z;
    float Ar[CNS], h[CNS], P[CNS];
#pragma unroll
    for (int n = 0; n < CNS; n++) {
        Ar[n] = -__expf(A_log[d * CNS + n]);
        h[n] = 0.0f;
        P[n] = 1.0f;
    }
    int t0 = chunk * CCL;
#pragma unroll 4
    for (int j = 0; j < CCL; j++) {
        int t = t0 + j;
        size_t row = (size_t)(b * CT + t);
        float dtv = g_dt[row * CDI + d];
        float xv  = g_xssm[row * CDI + d];
        float dtx = dtv * xv;
        const float* bp = g_xdbl + row * XD + CDTR;
#pragma unroll
        for (int n = 0; n < CNS; n++) {
            float dA = __expf(dtv * Ar[n]);
            h[n] = fmaf(dA, h[n], dtx * bp[n]);
            P[n] *= dA;
        }
    }
    size_t base = (((size_t)(b * CDI + d)) * CCH + chunk) * CNS;
#pragma unroll
    for (int n = 0; n < CNS; n++) { g_hend[base + n] = h[n]; g_prod[base + n] = P[n]; }
}

// ---------------- scan: sequential chunk combine ---------------------------
__global__ void scan_combine_kernel() {
    int idx = blockIdx.x * blockDim.x + threadIdx.x;  // over CB*CDI*CNS
    int n = idx & (CNS - 1);
    int bd = idx / CNS;
    size_t base = (size_t)bd * CCH * CNS + n;
    float H = 0.0f;
#pragma unroll 8
    for (int c = 0; c < CCH; c++) {
        g_hstart[base + (size_t)c * CNS] = H;
        H = fmaf(g_prod[base + (size_t)c * CNS], H, g_hend[base + (size_t)c * CNS]);
    }
}

// -------- scan: pass B (replay with true init; fused D-skip + SiLU gate) ---
__global__ void scan_passB_kernel(const float* __restrict__ A_log,
                                  const float* __restrict__ Dskip) {
    int d = blockIdx.x * blockDim.x + threadIdx.x;
    int chunk = blockIdx.y;
    int b = blockIdx.z;
    float Ar[CNS], h[CNS];
    size_t hbase = (((size_t)(b * CDI + d)) * CCH + chunk) * CNS;
#pragma unroll
    for (int n = 0; n < CNS; n++) {
        Ar[n] = -__expf(A_log[d * CNS + n]);
        h[n] = g_hstart[hbase + n];
    }
    float dsk = Dskip[d];
    int t0 = chunk * CCL;
#pragma unroll 4
    for (int j = 0; j < CCL; j++) {
        int t = t0 + j;
        size_t row = (size_t)(b * CT + t);
        float dtv = g_dt[row * CDI + d];
        float xv  = g_xssm[row * CDI + d];
        float dtx = dtv * xv;
        const float* bp = g_xdbl + row * XD + CDTR;
        const float* cp = bp + CNS;
        float y = 0.0f;
#pragma unroll
        for (int n = 0; n < CNS; n++) {
            float dA = __expf(dtv * Ar[n]);
            h[n] = fmaf(dA, h[n], dtx * bp[n]);
            y = fmaf(h[n], cp[n], y);
        }
        float zv = g_xz[row * (2 * CDI) + CDI + d];
        g_y[row * CDI + d] = (y + xv * dsk) * siluf(zv);
    }
}

// ---------------- host-side launcher ---------------------------------------
extern "C" void kernel_launch(void* const* d_in, const int* in_sizes, int n_in,
                              void* d_out, int out_size) {
    const int*   codes     = (const int*)d_in[0];
    const float* embed_w   = (const float*)d_in[1];
    const float* norm_w    = (const float*)d_in[2];
    const float* in_proj_w = (const float*)d_in[3];
    const float* conv_w    = (const float*)d_in[4];
    const float* conv_b    = (const float*)d_in[5];
    const float* x_proj_w  = (const float*)d_in[6];
    const float* dt_proj_w = (const float*)d_in[7];
    const float* dt_proj_b = (const float*)d_in[8];
    const float* A_log     = (const float*)d_in[9];
    const float* D_skip    = (const float*)d_in[10];
    const float* out_proj_w= (const float*)d_in[11];
    const float* head_w    = (const float*)d_in[12];
    float* out = (float*)d_out;

    float *px, *pxn, *pxz, *pxssm, *pxdpart, *pdt, *py;
    cudaGetSymbolAddress((void**)&px, g_x);
    cudaGetSymbolAddress((void**)&pxn, g_xn);
    cudaGetSymbolAddress((void**)&pxz, g_xz);
    cudaGetSymbolAddress((void**)&pxssm, g_xssm);
    cudaGetSymbolAddress((void**)&pxdpart, g_xdpart);
    cudaGetSymbolAddress((void**)&pdt, g_dt);
    cudaGetSymbolAddress((void**)&py, g_y);
    float* pxdbl; cudaGetSymbolAddress((void**)&pxdbl, g_xdbl);

    const int M = CB * CT;   // 2048 tokens

    // 1) RVQ sum-embedding
    embed_kernel<<<(CB * CT * CDM) / 256, 256>>>(codes, embed_w, px);

    for (int l = 0; l < CL; l++) {
        const float* nw  = norm_w    + (size_t)l * CDM;
        const float* iw  = in_proj_w + (size_t)l * 2 * CDI * CDM;
        const float* cw  = conv_w    + (size_t)l * CDI * CDC;
        const float* cb  = conv_b    + (size_t)l * CDI;
        const float* xpw = x_proj_w  + (size_t)l * XD * CDI;
        const float* dpw = dt_proj_w + (size_t)l * CDI * CDTR;
        const float* dpb = dt_proj_b + (size_t)l * CDI;
        const float* al  = A_log     + (size_t)l * CDI * CNS;
        const float* ds  = D_skip    + (size_t)l * CDI;
        const float* ow  = out_proj_w+ (size_t)l * CDM * CDI;

        // rmsnorm
        rmsnorm_kernel<<<M, 256>>>(px, nw, pxn);

        // in_proj (TF32 MMA): (2048 x 512) @ (2048 x 512)^T -> 2048 x 2048
        mma_gemm_kernel<0, true, 0>
            <<<dim3(2 * CDI / 128, M / 128, 1), 256>>>(
                pxn, iw, pxz, M, 2 * CDI, CDM, CDM, CDM, 2 * CDI, nullptr);

        // causal dwconv + silu
        conv_silu_kernel<<<(CB * CT * CDI) / 256, 256>>>(pxz, cw, cb);

        // x_proj (skinny, fp32): split-K=8 -> partials, then reduce
        sgemm_kernel<64, 64, 8, 4, 4, 0, true, 1>
            <<<dim3(1, M / 64, KSPLIT), 256>>>(
                pxssm, xpw, pxdpart, M, XD, CDI, CDI, CDI, XD, nullptr, nullptr, KSPLIT);
        reduce_xdbl_kernel<<<(CB * CT * XD) / 256, 256>>>();

        // dt = softplus(dt_lr @ dtp_w^T + b) (fp32):  (2048 x 32) @ (1024 x 32)^T
        sgemm_kernel<64, 64, 8, 4, 4, 1, true, 0>
            <<<dim3(CDI / 64, M / 64, 1), 256>>>(
                pxdbl, dpw, pdt, M, CDI, CDTR, XD, CDTR, CDI, dpb, nullptr, 1);

        // chunked parallel selective scan
        scan_passA_kernel<<<dim3(CDI / 256, CCH, CB), 256>>>(al);
        scan_combine_kernel<<<(CB * CDI * CNS) / 256, 256>>>();
        scan_passB_kernel<<<dim3(CDI / 256, CCH, CB), 256>>>(al, ds);

        // out_proj + residual (TF32 MMA): x = x + y @ ow^T
        mma_gemm_kernel<2, true, 0>
            <<<dim3(CDM / 128, M / 128, 1), 256>>>(
                py, ow, px, M, CDM, CDI, CDI, CDI, CDM, px);
    }

    // head (TF32 MMA, batched): out[b,k,t,v] = x[b,t,:] @ head_w[k]
    mma_gemm_kernel<0, false, 2>
        <<<dim3(CV / 128, CT / 128, CB * CK), 256>>>(
            px, head_w, out, CT, CV, CDM, CDM, CV, CV, nullptr);

    (void)in_sizes; (void)n_in; (void)out_size;
}

// round 5
// speedup vs baseline: 1.9666x; 1.2368x over previous
#include <cuda_runtime.h>
#include <cuda_bf16.h>
#include <cstdint>

// ---------------- problem constants ----------------
constexpr int CB   = 2;
constexpr int CK   = 4;
constexpr int CT   = 1024;
constexpr int CV   = 1024;
constexpr int CDM  = 512;
constexpr int CDI  = 1024;
constexpr int CNS  = 16;
constexpr int CDC  = 4;
constexpr int CDTR = 32;
constexpr int CL   = 2;
constexpr int CCH  = 64;
constexpr int CCL  = 16;
constexpr int XD   = CDTR + 2 * CNS;   // 64
constexpr int KSPLIT = 8;

constexpr int IW_ELE = CL * 2 * CDI * CDM;  // 2,097,152
constexpr int OW_ELE = CL * CDM * CDI;      // 1,048,576
constexpr int HW_ELE = CK * CDM * CV;       // 2,097,152

// ---------------- scratch ----------------
__device__ float g_x   [CB * CT * CDM];
__device__ float g_xn  [CB * CT * CDM];
__device__ float g_xz  [CB * CT * 2 * CDI];
__device__ float g_xssm[CB * CT * CDI];
__device__ float g_xdbl[CB * CT * XD];
__device__ float g_xdpart[KSPLIT * CB * CT * XD];
__device__ float g_dt  [CB * CT * CDI];
__device__ float g_y   [CB * CT * CDI];
__device__ float g_hend  [CB * CDI * CCH * CNS];
__device__ float g_prod  [CB * CDI * CCH * CNS];
__device__ float g_hstart[CB * CDI * CCH * CNS];
__device__ float g_iwr[IW_ELE];   // tf32-rounded in_proj weights
__device__ float g_owr[OW_ELE];   // tf32-rounded out_proj weights
__device__ float g_hwr[HW_ELE];   // tf32-rounded head weights

// ---------------- helpers ----------------
__device__ __forceinline__ float siluf(float x) { return x / (1.0f + __expf(-x)); }
__device__ __forceinline__ float softplusf(float x) {
    return fmaxf(x, 0.0f) + log1pf(__expf(-fabsf(x)));
}
// round fp32 -> nearest tf32-representable fp32 (low 13 mantissa bits zero)
__device__ __forceinline__ float tf32r(float x) {
    uint32_t u; asm("cvt.rna.tf32.f32 %0, %1;" : "=r"(u) : "f"(x));
    return __uint_as_float(u);
}
__device__ __forceinline__ void cp_async16(void* smem_dst, const void* gsrc) {
    uint32_t s = (uint32_t)__cvta_generic_to_shared(smem_dst);
    asm volatile("cp.async.ca.shared.global [%0], [%1], 16;" :: "r"(s), "l"(gsrc));
}

// ---------------- weight tf32 pre-round ----------------
__global__ void round_weights_kernel(const float* __restrict__ iw,
                                     const float* __restrict__ ow,
                                     const float* __restrict__ hw) {
    int idx = blockIdx.x * 256 + threadIdx.x;
    if (idx < IW_ELE) g_iwr[idx] = tf32r(iw[idx]);
    if (idx < OW_ELE) g_owr[idx] = tf32r(ow[idx]);
    if (idx < HW_ELE) g_hwr[idx] = tf32r(hw[idx]);
}
__global__ void round_x_kernel(const float* __restrict__ src, float* __restrict__ dst) {
    int idx = blockIdx.x * 256 + threadIdx.x;
    dst[idx] = tf32r(src[idx]);
}

// ---------------- embedding ----------------
__global__ void embed_kernel(const int* __restrict__ codes,
                             const float* __restrict__ ew,
                             float* __restrict__ xout) {
    int idx = blockIdx.x * blockDim.x + threadIdx.x;
    int d  = idx & (CDM - 1);
    int bt = idx / CDM;
    int t  = bt & (CT - 1);
    int b  = bt / CT;
    float s = 0.0f;
#pragma unroll
    for (int k = 0; k < CK; k++) {
        int code = codes[(b * CK + k) * CT + t];
        s += ew[((size_t)k * CV + code) * CDM + d];
    }
    xout[idx] = s;
}

// ---------------- rmsnorm (tf32-rounded output: feeds in_proj A only) -----
__global__ void rmsnorm_kernel(const float* __restrict__ x,
                               const float* __restrict__ w,
                               float* __restrict__ out) {
    int tok = blockIdx.x;
    int tid = threadIdx.x;
    const float* xr = x + (size_t)tok * CDM;
    float v0 = xr[tid], v1 = xr[tid + 256];
    float ss = v0 * v0 + v1 * v1;
#pragma unroll
    for (int off = 16; off; off >>= 1) ss += __shfl_xor_sync(0xffffffffu, ss, off);
    __shared__ float red[8];
    if ((tid & 31) == 0) red[tid >> 5] = ss;
    __syncthreads();
    float tot = 0.0f;
#pragma unroll
    for (int i = 0; i < 8; i++) tot += red[i];
    float r = rsqrtf(tot * (1.0f / CDM) + 1e-6f);
    float* orow = out + (size_t)tok * CDM;
    orow[tid]       = tf32r(v0 * w[tid] * r);
    orow[tid + 256] = tf32r(v1 * w[tid + 256] * r);
}

// ====================================================================
// TF32 MMA GEMM, cp.async double-buffered. Inputs MUST be pre-rounded
// to tf32-representable fp32 (HW truncation is then lossless/RNA).
// C[m,n] = epi( sum_k A[m,k] * B(n,k) ); NT: B row-major NxK; !NT: KxN.
// EPI: 0 plain, 2 residual add. ZMODE 2: batched head (z = b*CK+k).
// BM=128 fixed, BK=16, 8 warps, warp tile 32 x (BN/2).
// ====================================================================
template<int BN, int EPI, bool NT, int ZMODE>
__global__ __launch_bounds__(256)
void mma_async_kernel(const float* __restrict__ A, const float* __restrict__ B,
                      float* __restrict__ C, int M, int N, int K,
                      int lda, int ldb, int ldc, const float* __restrict__ res) {
    constexpr int BM = 128, BK = 16;
    constexpr int WN = BN / 2, NI = WN / 8;
    constexpr int AST = 20;                      // A row stride (words), pad 16+4
    constexpr int BST = NT ? 20 : 136;           // B stride (words)
    constexpr int AWORDS = BM * AST;
    constexpr int BWORDS = NT ? BN * AST : BK * 136;
    constexpr int BCHUNK = BN * BK / 4;          // 16B chunks in B tile

    __shared__ float As[2][AWORDS];
    __shared__ float Bs[2][BWORDS];

    int tid  = threadIdx.x;
    int warp = tid >> 5, lane = tid & 31;
    int q = lane & 3, g = lane >> 2;
    int wm = (warp >> 1) * 32, wn = (warp & 1) * WN;
    int bm = blockIdx.y * BM, bn = blockIdx.x * BN;

    if (ZMODE == 2) {
        int zb = blockIdx.z >> 2, zk = blockIdx.z & 3;
        A += (size_t)zb * CT * CDM;
        B += (size_t)zk * CDM * CV;
        C += (size_t)blockIdx.z * CT * CV;
    }

    auto loadA = [&](int st, int kb) {
#pragma unroll
        for (int ch = tid; ch < 512; ch += 256) {
            int r = ch >> 2, c = (ch & 3) * 4;
            cp_async16(&As[st][r * AST + c], A + (size_t)(bm + r) * lda + kb + c);
        }
    };
    auto loadB = [&](int st, int kb) {
        if (NT) {
#pragma unroll
            for (int ch = tid; ch < BCHUNK; ch += 256) {
                int r = ch >> 2, c = (ch & 3) * 4;
                cp_async16(&Bs[st][r * BST + c], B + (size_t)(bn + r) * ldb + kb + c);
            }
        } else {
#pragma unroll
            for (int ch = tid; ch < BCHUNK; ch += 256) {
                int r = ch >> 5, c = (ch & 31) * 4;
                cp_async16(&Bs[st][r * BST + c], B + (size_t)(kb + r) * ldb + bn + c);
            }
        }
    };

    float c[2][NI][4];
#pragma unroll
    for (int mi = 0; mi < 2; mi++)
#pragma unroll
        for (int ni = 0; ni < NI; ni++)
#pragma unroll
            for (int j = 0; j < 4; j++) c[mi][ni][j] = 0.0f;

    int niter = K / BK;
    loadA(0, 0); loadB(0, 0);
    asm volatile("cp.async.commit_group;" ::: "memory");

    for (int it = 0; it < niter; it++) {
        int st = it & 1;
        if (it + 1 < niter) {
            loadA(st ^ 1, (it + 1) * BK);
            loadB(st ^ 1, (it + 1) * BK);
            asm volatile("cp.async.commit_group;" ::: "memory");
            asm volatile("cp.async.wait_group 1;" ::: "memory");
        } else {
            asm volatile("cp.async.wait_group 0;" ::: "memory");
        }
        __syncthreads();

#pragma unroll
        for (int kk = 0; kk < BK; kk += 8) {
            int k0 = kk + q;
            uint32_t af[2][4], bf[NI][2];
#pragma unroll
            for (int mi = 0; mi < 2; mi++) {
                int m = wm + mi * 16 + g;
                af[mi][0] = __float_as_uint(As[st][m * AST + k0]);
                af[mi][1] = __float_as_uint(As[st][(m + 8) * AST + k0]);
                af[mi][2] = __float_as_uint(As[st][m * AST + k0 + 4]);
                af[mi][3] = __float_as_uint(As[st][(m + 8) * AST + k0 + 4]);
            }
#pragma unroll
            for (int ni = 0; ni < NI; ni++) {
                int n = wn + ni * 8 + g;
                if (NT) {
                    bf[ni][0] = __float_as_uint(Bs[st][n * BST + k0]);
                    bf[ni][1] = __float_as_uint(Bs[st][n * BST + k0 + 4]);
                } else {
                    bf[ni][0] = __float_as_uint(Bs[st][k0 * BST + n]);
                    bf[ni][1] = __float_as_uint(Bs[st][(k0 + 4) * BST + n]);
                }
            }
#pragma unroll
            for (int mi = 0; mi < 2; mi++)
#pragma unroll
                for (int ni = 0; ni < NI; ni++) {
                    asm volatile(
                        "mma.sync.aligned.m16n8k8.row.col.f32.tf32.tf32.f32 "
                        "{%0,%1,%2,%3}, {%4,%5,%6,%7}, {%8,%9}, {%0,%1,%2,%3};"
                        : "+f"(c[mi][ni][0]), "+f"(c[mi][ni][1]),
                          "+f"(c[mi][ni][2]), "+f"(c[mi][ni][3])
                        : "r"(af[mi][0]), "r"(af[mi][1]), "r"(af[mi][2]), "r"(af[mi][3]),
                          "r"(bf[ni][0]), "r"(bf[ni][1]));
                }
        }
        __syncthreads();
    }

    // ---- epilogue ----
#pragma unroll
    for (int mi = 0; mi < 2; mi++) {
        int m0 = bm + wm + mi * 16 + g;
#pragma unroll
        for (int ni = 0; ni < NI; ni++) {
            int n0 = bn + wn + ni * 8 + q * 2;
            float2 v0 = make_float2(c[mi][ni][0], c[mi][ni][1]);
            float2 v1 = make_float2(c[mi][ni][2], c[mi][ni][3]);
            if (EPI == 2) {
                const float* r0 = res + (size_t)m0 * ldc + n0;
                const float* r1 = res + (size_t)(m0 + 8) * ldc + n0;
                v0.x += r0[0]; v0.y += r0[1];
                v1.x += r1[0]; v1.y += r1[1];
            }
            *reinterpret_cast<float2*>(C + (size_t)m0 * ldc + n0)       = v0;
            *reinterpret_cast<float2*>(C + (size_t)(m0 + 8) * ldc + n0) = v1;
        }
    }
}

// ---------------- fp32 SGEMM (skinny GEMMs) ----------------
template<int BM, int BN, int BK, int TM, int TN, int EPI, bool NT, int ZMODE>
__global__ __launch_bounds__((BM / TM) * (BN / TN))
void sgemm_kernel(const float* __restrict__ A, const float* __restrict__ B,
                  float* __restrict__ C, int M, int N, int Kt,
                  int lda, int ldb, int ldc,
                  const float* __restrict__ bias, const float* __restrict__ res,
                  int nsplit) {
    constexpr int THREADS = (BM / TM) * (BN / TN);
    __shared__ float As[BK][BM];
    __shared__ float Bs[BK][BN];
    int tid = threadIdx.x;
    int bn = blockIdx.x * BN, bm = blockIdx.y * BM;
    int k_begin = 0, k_end = Kt;
    if (ZMODE == 1) {
        int ks = Kt / nsplit;
        k_begin = blockIdx.z * ks;
        k_end   = k_begin + ks;
        C += (size_t)blockIdx.z * M * ldc;
    }
    constexpr int BNT = BN / TN;
    int tc = tid % BNT, tr = tid / BNT;
    float acc[TM][TN];
#pragma unroll
    for (int i = 0; i < TM; i++)
#pragma unroll
        for (int j = 0; j < TN; j++) acc[i][j] = 0.0f;

    for (int kb = k_begin; kb < k_end; kb += BK) {
#pragma unroll
        for (int i = tid * 4; i < BM * BK; i += THREADS * 4) {
            int r = i / BK, c = i % BK;
            float4 v = *reinterpret_cast<const float4*>(A + (size_t)(bm + r) * lda + kb + c);
            As[c + 0][r] = v.x; As[c + 1][r] = v.y;
            As[c + 2][r] = v.z; As[c + 3][r] = v.w;
        }
        if (NT) {
#pragma unroll
            for (int i = tid * 4; i < BN * BK; i += THREADS * 4) {
                int r = i / BK, c = i % BK;
                float4 v = make_float4(0.f, 0.f, 0.f, 0.f);
                if (bn + r < N)
                    v = *reinterpret_cast<const float4*>(B + (size_t)(bn + r) * ldb + kb + c);
                Bs[c + 0][r] = v.x; Bs[c + 1][r] = v.y;
                Bs[c + 2][r] = v.z; Bs[c + 3][r] = v.w;
            }
        } else {
#pragma unroll
            for (int i = tid * 4; i < BK * BN; i += THREADS * 4) {
                int r = i / BN, c = i % BN;
                float4 v = *reinterpret_cast<const float4*>(B + (size_t)(kb + r) * ldb + bn + c);
                *reinterpret_cast<float4*>(&Bs[r][c]) = v;
            }
        }
        __syncthreads();
#pragma unroll
        for (int kk = 0; kk < BK; kk++) {
            float a[TM], bf[TN];
#pragma unroll
            for (int i = 0; i < TM; i++) a[i] = As[kk][tr * TM + i];
#pragma unroll
            for (int j = 0; j < TN; j++) bf[j] = Bs[kk][tc * TN + j];
#pragma unroll
            for (int i = 0; i < TM; i++)
#pragma unroll
                for (int j = 0; j < TN; j++) acc[i][j] = fmaf(a[i], bf[j], acc[i][j]);
        }
        __syncthreads();
    }
#pragma unroll
    for (int i = 0; i < TM; i++) {
        int m = bm + tr * TM + i;
#pragma unroll
        for (int j = 0; j < TN; j++) {
            int n = bn + tc * TN + j;
            if (n < N) {
                float v = acc[i][j];
                if (EPI == 1) { v += bias[n]; v = softplusf(v); }
                if (EPI == 2) { v += res[(size_t)m * ldc + n]; }
                C[(size_t)m * ldc + n] = v;
            }
        }
    }
}

// ---------------- split-K reduction ----------------
__global__ void reduce_xdbl_kernel() {
    int idx = blockIdx.x * blockDim.x + threadIdx.x;
    float s = 0.0f;
#pragma unroll
    for (int z = 0; z < KSPLIT; z++) s += g_xdpart[(size_t)z * CB * CT * XD + idx];
    g_xdbl[idx] = s;
}

// ---------------- causal dwconv + SiLU ----------------
__global__ void conv_silu_kernel(const float* __restrict__ xz,
                                 const float* __restrict__ cw,
                                 const float* __restrict__ cb) {
    int idx = blockIdx.x * blockDim.x + threadIdx.x;
    int d = idx & (CDI - 1);
    int bt = idx / CDI;
    int t = bt & (CT - 1);
    int b = bt / CT;
    const float* w = cw + d * CDC;
    float acc = cb[d];
#pragma unroll
    for (int j = 0; j < CDC; j++) {
        int tt = t - (CDC - 1) + j;
        if (tt >= 0) acc += w[j] * xz[((size_t)(b * CT + tt)) * (2 * CDI) + d];
    }
    g_xssm[idx] = siluf(acc);
}

// ---------------- scan pass A ----------------
__global__ void scan_passA_kernel(const float* __restrict__ A_log) {
    int d = blockIdx.x * blockDim.x + threadIdx.x;
    int chunk = blockIdx.y;
    int b = blockIdx.z;
    float Ar[CNS], h[CNS], P[CNS];
#pragma unroll
    for (int n = 0; n < CNS; n++) {
        Ar[n] = -__expf(A_log[d * CNS + n]);
        h[n] = 0.0f;
        P[n] = 1.0f;
    }
    int t0 = chunk * CCL;
#pragma unroll 4
    for (int j = 0; j < CCL; j++) {
        int t = t0 + j;
        size_t row = (size_t)(b * CT + t);
        float dtv = g_dt[row * CDI + d];
        float xv  = g_xssm[row * CDI + d];
        float dtx = dtv * xv;
        const float* bp = g_xdbl + row * XD + CDTR;
#pragma unroll
        for (int n = 0; n < CNS; n++) {
            float dA = __expf(dtv * Ar[n]);
            h[n] = fmaf(dA, h[n], dtx * bp[n]);
            P[n] *= dA;
        }
    }
    size_t base = (((size_t)(b * CDI + d)) * CCH + chunk) * CNS;
#pragma unroll
    for (int n = 0; n < CNS; n++) { g_hend[base + n] = h[n]; g_prod[base + n] = P[n]; }
}

// ---------------- scan combine ----------------
__global__ void scan_combine_kernel() {
    int idx = blockIdx.x * blockDim.x + threadIdx.x;
    int n = idx & (CNS - 1);
    int bd = idx / CNS;
    size_t base = (size_t)bd * CCH * CNS + n;
    float H = 0.0f;
#pragma unroll 8
    for (int c = 0; c < CCH; c++) {
        g_hstart[base + (size_t)c * CNS] = H;
        H = fmaf(g_prod[base + (size_t)c * CNS], H, g_hend[base + (size_t)c * CNS]);
    }
}

// ---------------- scan pass B (tf32-rounded output: feeds out_proj A) -----
__global__ void scan_passB_kernel(const float* __restrict__ A_log,
                                  const float* __restrict__ Dskip) {
    int d = blockIdx.x * blockDim.x + threadIdx.x;
    int chunk = blockIdx.y;
    int b = blockIdx.z;
    float Ar[CNS], h[CNS];
    size_t hbase = (((size_t)(b * CDI + d)) * CCH + chunk) * CNS;
#pragma unroll
    for (int n = 0; n < CNS; n++) {
        Ar[n] = -__expf(A_log[d * CNS + n]);
        h[n] = g_hstart[hbase + n];
    }
    float dsk = Dskip[d];
    int t0 = chunk * CCL;
#pragma unroll 4
    for (int j = 0; j < CCL; j++) {
        int t = t0 + j;
        size_t row = (size_t)(b * CT + t);
        float dtv = g_dt[row * CDI + d];
        float xv  = g_xssm[row * CDI + d];
        float dtx = dtv * xv;
        const float* bp = g_xdbl + row * XD + CDTR;
        const float* cp = bp + CNS;
        float y = 0.0f;
#pragma unroll
        for (int n = 0; n < CNS; n++) {
            float dA = __expf(dtv * Ar[n]);
            h[n] = fmaf(dA, h[n], dtx * bp[n]);
            y = fmaf(h[n], cp[n], y);
        }
        float zv = g_xz[row * (2 * CDI) + CDI + d];
        g_y[row * CDI + d] = tf32r((y + xv * dsk) * siluf(zv));
    }
}

// ---------------- host launcher ----------------
extern "C" void kernel_launch(void* const* d_in, const int* in_sizes, int n_in,
                              void* d_out, int out_size) {
    const int*   codes     = (const int*)d_in[0];
    const float* embed_w   = (const float*)d_in[1];
    const float* norm_w    = (const float*)d_in[2];
    const float* in_proj_w = (const float*)d_in[3];
    const float* conv_w    = (const float*)d_in[4];
    const float* conv_b    = (const float*)d_in[5];
    const float* x_proj_w  = (const float*)d_in[6];
    const float* dt_proj_w = (const float*)d_in[7];
    const float* dt_proj_b = (const float*)d_in[8];
    const float* A_log     = (const float*)d_in[9];
    const float* D_skip    = (const float*)d_in[10];
    const float* out_proj_w= (const float*)d_in[11];
    const float* head_w    = (const float*)d_in[12];
    float* out = (float*)d_out;

    float *px, *pxn, *pxz, *pxssm, *pxdpart, *pdt, *py, *pxdbl;
    float *piwr, *powr, *phwr;
    cudaGetSymbolAddress((void**)&px, g_x);
    cudaGetSymbolAddress((void**)&pxn, g_xn);
    cudaGetSymbolAddress((void**)&pxz, g_xz);
    cudaGetSymbolAddress((void**)&pxssm, g_xssm);
    cudaGetSymbolAddress((void**)&pxdpart, g_xdpart);
    cudaGetSymbolAddress((void**)&pdt, g_dt);
    cudaGetSymbolAddress((void**)&py, g_y);
    cudaGetSymbolAddress((void**)&pxdbl, g_xdbl);
    cudaGetSymbolAddress((void**)&piwr, g_iwr);
    cudaGetSymbolAddress((void**)&powr, g_owr);
    cudaGetSymbolAddress((void**)&phwr, g_hwr);

    const int M = CB * CT;   // 2048

    // weight tf32 pre-round + embedding
    round_weights_kernel<<<(IW_ELE + 255) / 256, 256>>>(in_proj_w, out_proj_w, head_w);
    embed_kernel<<<(CB * CT * CDM) / 256, 256>>>(codes, embed_w, px);

    for (int l = 0; l < CL; l++) {
        const float* nw  = norm_w    + (size_t)l * CDM;
        const float* cw  = conv_w    + (size_t)l * CDI * CDC;
        const float* cb  = conv_b    + (size_t)l * CDI;
        const float* xpw = x_proj_w  + (size_t)l * XD * CDI;
        const float* dpw = dt_proj_w + (size_t)l * CDI * CDTR;
        const float* dpb = dt_proj_b + (size_t)l * CDI;
        const float* al  = A_log     + (size_t)l * CDI * CNS;
        const float* ds  = D_skip    + (size_t)l * CDI;
        const float* iwr = piwr + (size_t)l * 2 * CDI * CDM;
        const float* owr = powr + (size_t)l * CDM * CDI;

        rmsnorm_kernel<<<M, 256>>>(px, nw, pxn);

        // in_proj (tf32 MMA, async): 2048x512 @ (2048x512)^T
        mma_async_kernel<128, 0, true, 0>
            <<<dim3(2 * CDI / 128, M / 128, 1), 256>>>(
                pxn, iwr, pxz, M, 2 * CDI, CDM, CDM, CDM, 2 * CDI, nullptr);

        conv_silu_kernel<<<(CB * CT * CDI) / 256, 256>>>(pxz, cw, cb);

        // x_proj (skinny, fp32): split-K=8
        sgemm_kernel<64, 64, 8, 4, 4, 0, true, 1>
            <<<dim3(1, M / 64, KSPLIT), 256>>>(
                pxssm, xpw, pxdpart, M, XD, CDI, CDI, CDI, XD, nullptr, nullptr, KSPLIT);
        reduce_xdbl_kernel<<<(CB * CT * XD) / 256, 256>>>();

        // dt = softplus(dt_lr @ dtp_w^T + b)
        sgemm_kernel<64, 64, 8, 4, 4, 1, true, 0>
            <<<dim3(CDI / 64, M / 64, 1), 256>>>(
                pxdbl, dpw, pdt, M, CDI, CDTR, XD, CDTR, CDI, dpb, nullptr, 1);

        // chunked parallel selective scan
        scan_passA_kernel<<<dim3(CDI / 256, CCH, CB), 256>>>(al);
        scan_combine_kernel<<<(CB * CDI * CNS) / 256, 256>>>();
        scan_passB_kernel<<<dim3(CDI / 256, CCH, CB), 256>>>(al, ds);

        // out_proj + residual (tf32 MMA, BN=64 for occupancy)
        mma_async_kernel<64, 2, true, 0>
            <<<dim3(CDM / 64, M / 128, 1), 256>>>(
                py, owr, px, M, CDM, CDI, CDI, CDI, CDM, px);
    }

    // round final residual for head A (g_xn is free here)
    round_x_kernel<<<(CB * CT * CDM) / 256, 256>>>(px, pxn);

    // head (tf32 MMA, NN, batched z = b*CK + k)
    mma_async_kernel<128, 0, false, 2>
        <<<dim3(CV / 128, CT / 128, CB * CK), 256>>>(
            pxn, phwr, out, CT, CV, CDM, CDM, CV, CV, nullptr);

    (void)in_sizes; (void)n_in; (void)out_size;
}

// round 7
// speedup vs baseline: 2.0544x; 1.0446x over previous
#include <cuda_runtime.h>
#include <cuda_bf16.h>
#include <cstdint>

// ---------------- problem constants ----------------
constexpr int CB   = 2;
constexpr int CK   = 4;
constexpr int CT   = 1024;
constexpr int CV   = 1024;
constexpr int CDM  = 512;
constexpr int CDI  = 1024;
constexpr int CNS  = 16;
constexpr int CDC  = 4;
constexpr int CDTR = 32;
constexpr int CL   = 2;
constexpr int CCH  = 64;
constexpr int CCL  = 16;
constexpr int XD   = CDTR + 2 * CNS;   // 64
constexpr int KSPLIT = 4;              // split-K factor for x_proj MMA

constexpr int IW_ELE = CL * 2 * CDI * CDM;  // 2,097,152
constexpr int OW_ELE = CL * CDM * CDI;      // 1,048,576
constexpr int HW_ELE = CK * CDM * CV;       // 2,097,152
constexpr int XP_ELE = CL * XD * CDI;       // 131,072

// ---------------- scratch ----------------
__device__ float g_x   [CB * CT * CDM];
__device__ float g_xn  [CB * CT * CDM];
__device__ float g_xz  [CB * CT * 2 * CDI];
__device__ float g_xssm[CB * CT * CDI];
__device__ float g_xdbl[CB * CT * XD];
__device__ float g_xdpart[KSPLIT * CB * CT * XD];
__device__ float g_dt  [CB * CT * CDI];
__device__ float g_y   [CB * CT * CDI];
__device__ float g_hend  [CB * CDI * CCH * CNS];
__device__ float g_prod  [CB * CDI * CCH * CNS];
__device__ float g_hstart[CB * CDI * CCH * CNS];
__device__ float g_iwr[IW_ELE];   // tf32-rounded in_proj weights
__device__ float g_owr[OW_ELE];   // tf32-rounded out_proj weights
__device__ float g_hwr[HW_ELE];   // tf32-rounded head weights
__device__ float g_xpr[XP_ELE];   // tf32-rounded x_proj weights

// ---------------- helpers ----------------
__device__ __forceinline__ float siluf(float x) { return x / (1.0f + __expf(-x)); }
__device__ __forceinline__ float softplusf(float x) {
    return fmaxf(x, 0.0f) + log1pf(__expf(-fabsf(x)));
}
// round fp32 -> nearest tf32-representable fp32
__device__ __forceinline__ float tf32r(float x) {
    uint32_t u; asm("cvt.rna.tf32.f32 %0, %1;" : "=r"(u) : "f"(x));
    return __uint_as_float(u);
}
__device__ __forceinline__ void cp_async16(void* smem_dst, const void* gsrc) {
    uint32_t s = (uint32_t)__cvta_generic_to_shared(smem_dst);
    asm volatile("cp.async.ca.shared.global [%0], [%1], 16;" :: "r"(s), "l"(gsrc));
}

// ---------------- weight tf32 pre-round ----------------
__global__ void round_weights_kernel(const float* __restrict__ iw,
                                     const float* __restrict__ ow,
                                     const float* __restrict__ hw,
                                     const float* __restrict__ xp) {
    int idx = blockIdx.x * 256 + threadIdx.x;
    if (idx < IW_ELE) g_iwr[idx] = tf32r(iw[idx]);
    if (idx < OW_ELE) g_owr[idx] = tf32r(ow[idx]);
    if (idx < HW_ELE) g_hwr[idx] = tf32r(hw[idx]);
    if (idx < XP_ELE) g_xpr[idx] = tf32r(xp[idx]);
}

// ---------------- embedding ----------------
__global__ void embed_kernel(const int* __restrict__ codes,
                             const float* __restrict__ ew,
                             float* __restrict__ xout) {
    int idx = blockIdx.x * blockDim.x + threadIdx.x;
    int d  = idx & (CDM - 1);
    int bt = idx / CDM;
    int t  = bt & (CT - 1);
    int b  = bt / CT;
    float s = 0.0f;
#pragma unroll
    for (int k = 0; k < CK; k++) {
        int code = codes[(b * CK + k) * CT + t];
        s += ew[((size_t)k * CV + code) * CDM + d];
    }
    xout[idx] = s;
}

// ---------------- rmsnorm (tf32-rounded output: feeds in_proj A) ----------
__global__ void rmsnorm_kernel(const float* __restrict__ x,
                               const float* __restrict__ w,
                               float* __restrict__ out) {
    int tok = blockIdx.x;
    int tid = threadIdx.x;
    const float* xr = x + (size_t)tok * CDM;
    float v0 = xr[tid], v1 = xr[tid + 256];
    float ss = v0 * v0 + v1 * v1;
#pragma unroll
    for (int off = 16; off; off >>= 1) ss += __shfl_xor_sync(0xffffffffu, ss, off);
    __shared__ float red[8];
    if ((tid & 31) == 0) red[tid >> 5] = ss;
    __syncthreads();
    float tot = 0.0f;
#pragma unroll
    for (int i = 0; i < 8; i++) tot += red[i];
    float r = rsqrtf(tot * (1.0f / CDM) + 1e-6f);
    float* orow = out + (size_t)tok * CDM;
    orow[tid]       = tf32r(v0 * w[tid] * r);
    orow[tid + 256] = tf32r(v1 * w[tid + 256] * r);
}

// ====================================================================
// TF32 MMA GEMM, 3-stage cp.async pipeline, ONE syncthreads per K-tile.
// Inputs must be pre-rounded to tf32-representable fp32.
// C[m,n] = epi( sum_k A[m,k] * B(n,k) ); NT: B row-major NxK; !NT: KxN.
// EPI: 0 plain, 2 residual add, 3 residual add + tf32-rounded copy to C2.
// ZMODE: 0 none, 1 split-K via blockIdx.z (partials), 2 batched head.
// BM=128, BK=16, 8 warps, warp tile 32 x (BN/2). Dynamic smem.
// ====================================================================
template<int BN, int EPI, bool NT, int ZMODE>
__global__ __launch_bounds__(256)
void mma3_kernel(const float* __restrict__ A, const float* __restrict__ B,
                 float* __restrict__ C, float* __restrict__ C2,
                 int M, int N, int K,
                 int lda, int ldb, int ldc, const float* __restrict__ res) {
    constexpr int BM = 128, BK = 16, STAGES = 3;
    constexpr int WN = BN / 2, NI = WN / 8;
    constexpr int AST = 20;                   // A row stride (words)
    constexpr int BST = NT ? 20 : 136;        // B stride (words)
    constexpr int AWORDS = BM * AST;
    constexpr int BWORDS = NT ? BN * AST : BK * BST;
    constexpr int BCHUNK = BN * BK / 4;       // 16B chunks in B tile

    extern __shared__ float sm[];
    float* Asm = sm;                          // [STAGES][AWORDS]
    float* Bsm = sm + STAGES * AWORDS;        // [STAGES][BWORDS]

    int tid  = threadIdx.x;
    int warp = tid >> 5, lane = tid & 31;
    int q = lane & 3, g = lane >> 2;
    int wm = (warp >> 1) * 32, wn = (warp & 1) * WN;
    int bm = blockIdx.y * BM, bn = blockIdx.x * BN;

    int k_begin = 0, k_count = K;
    if (ZMODE == 1) {
        int Kc = K / gridDim.z;
        k_begin = blockIdx.z * Kc;
        k_count = Kc;
        C += (size_t)blockIdx.z * M * ldc;
    }
    if (ZMODE == 2) {
        int zb = blockIdx.z >> 2, zk = blockIdx.z & 3;
        A += (size_t)zb * CT * CDM;
        B += (size_t)zk * CDM * CV;
        C += (size_t)blockIdx.z * CT * CV;
    }

    auto loadA = [&](int st, int kb) {
        float* dst = Asm + st * AWORDS;
#pragma unroll
        for (int ch = tid; ch < 512; ch += 256) {
            int r = ch >> 2, c = (ch & 3) * 4;
            cp_async16(dst + r * AST + c, A + (size_t)(bm + r) * lda + kb + c);
        }
    };
    auto loadB = [&](int st, int kb) {
        float* dst = Bsm + st * BWORDS;
        if (NT) {
#pragma unroll
            for (int ch = tid; ch < BCHUNK; ch += 256) {
                int r = ch >> 2, c = (ch & 3) * 4;
                cp_async16(dst + r * BST + c, B + (size_t)(bn + r) * ldb + kb + c);
            }
        } else {
#pragma unroll
            for (int ch = tid; ch < BCHUNK; ch += 256) {
                int r = ch >> 5, c = (ch & 31) * 4;
                cp_async16(dst + r * BST + c, B + (size_t)(kb + r) * ldb + bn + c);
            }
        }
    };

    float c[2][NI][4];
#pragma unroll
    for (int mi = 0; mi < 2; mi++)
#pragma unroll
        for (int ni = 0; ni < NI; ni++)
#pragma unroll
            for (int j = 0; j < 4; j++) c[mi][ni][j] = 0.0f;

    int niter = k_count / BK;

    // prologue: prefetch stages 0 and 1
    loadA(0, k_begin); loadB(0, k_begin);
    asm volatile("cp.async.commit_group;" ::: "memory");
    if (niter > 1) { loadA(1, k_begin + BK); loadB(1, k_begin + BK); }
    asm volatile("cp.async.commit_group;" ::: "memory");

    for (int it = 0; it < niter; it++) {
        asm volatile("cp.async.wait_group 1;" ::: "memory");
        __syncthreads();

        // issue stage it+2 (overwrites stage consumed at it-1; all warps past barrier)
        if (it + 2 < niter) {
            int st2 = (it + 2) % STAGES;
            loadA(st2, k_begin + (it + 2) * BK);
            loadB(st2, k_begin + (it + 2) * BK);
        }
        asm volatile("cp.async.commit_group;" ::: "memory");

        int st = it % STAGES;
        const float* Ast = Asm + st * AWORDS;
        const float* Bst = Bsm + st * BWORDS;

#pragma unroll
        for (int kk = 0; kk < BK; kk += 8) {
            int k0 = kk + q;
            uint32_t af[2][4], bf[NI][2];
#pragma unroll
            for (int mi = 0; mi < 2; mi++) {
                int m = wm + mi * 16 + g;
                af[mi][0] = __float_as_uint(Ast[m * AST + k0]);
                af[mi][1] = __float_as_uint(Ast[(m + 8) * AST + k0]);
                af[mi][2] = __float_as_uint(Ast[m * AST + k0 + 4]);
                af[mi][3] = __float_as_uint(Ast[(m + 8) * AST + k0 + 4]);
            }
#pragma unroll
            for (int ni = 0; ni < NI; ni++) {
                int n = wn + ni * 8 + g;
                if (NT) {
                    bf[ni][0] = __float_as_uint(Bst[n * BST + k0]);
                    bf[ni][1] = __float_as_uint(Bst[n * BST + k0 + 4]);
                } else {
                    bf[ni][0] = __float_as_uint(Bst[k0 * BST + n]);
                    bf[ni][1] = __float_as_uint(Bst[(k0 + 4) * BST + n]);
                }
            }
#pragma unroll
            for (int mi = 0; mi < 2; mi++)
#pragma unroll
                for (int ni = 0; ni < NI; ni++) {
                    asm volatile(
                        "mma.sync.aligned.m16n8k8.row.col.f32.tf32.tf32.f32 "
                        "{%0,%1,%2,%3}, {%4,%5,%6,%7}, {%8,%9}, {%0,%1,%2,%3};"
                        : "+f"(c[mi][ni][0]), "+f"(c[mi][ni][1]),
                          "+f"(c[mi][ni][2]), "+f"(c[mi][ni][3])
                        : "r"(af[mi][0]), "r"(af[mi][1]), "r"(af[mi][2]), "r"(af[mi][3]),
                          "r"(bf[ni][0]), "r"(bf[ni][1]));
                }
        }
        __syncthreads();
    }

    // ---- epilogue ----
#pragma unroll
    for (int mi = 0; mi < 2; mi++) {
        int m0 = bm + wm + mi * 16 + g;
#pragma unroll
        for (int ni = 0; ni < NI; ni++) {
            int n0 = bn + wn + ni * 8 + q * 2;
            float2 v0 = make_float2(c[mi][ni][0], c[mi][ni][1]);
            float2 v1 = make_float2(c[mi][ni][2], c[mi][ni][3]);
            if (EPI == 2 || EPI == 3) {
                const float* r0 = res + (size_t)m0 * ldc + n0;
                const float* r1 = res + (size_t)(m0 + 8) * ldc + n0;
                v0.x += r0[0]; v0.y += r0[1];
                v1.x += r1[0]; v1.y += r1[1];
            }
            *reinterpret_cast<float2*>(C + (size_t)m0 * ldc + n0)       = v0;
            *reinterpret_cast<float2*>(C + (size_t)(m0 + 8) * ldc + n0) = v1;
            if (EPI == 3) {
                float2 w0 = make_float2(tf32r(v0.x), tf32r(v0.y));
                float2 w1 = make_float2(tf32r(v1.x), tf32r(v1.y));
                *reinterpret_cast<float2*>(C2 + (size_t)m0 * ldc + n0)       = w0;
                *reinterpret_cast<float2*>(C2 + (size_t)(m0 + 8) * ldc + n0) = w1;
            }
        }
    }
}

// ---------------- fp32 SGEMM (dt_proj only: K=32) ----------------
template<int BM, int BN, int BK, int TM, int TN, int EPI>
__global__ __launch_bounds__((BM / TM) * (BN / TN))
void sgemm_kernel(const float* __restrict__ A, const float* __restrict__ B,
                  float* __restrict__ C, int M, int N, int Kt,
                  int lda, int ldb, int ldc,
                  const float* __restrict__ bias) {
    constexpr int THREADS = (BM / TM) * (BN / TN);
    __shared__ float As[BK][BM];
    __shared__ float Bs[BK][BN];
    int tid = threadIdx.x;
    int bn = blockIdx.x * BN, bm = blockIdx.y * BM;
    constexpr int BNT = BN / TN;
    int tc = tid % BNT, tr = tid / BNT;
    float acc[TM][TN];
#pragma unroll
    for (int i = 0; i < TM; i++)
#pragma unroll
        for (int j = 0; j < TN; j++) acc[i][j] = 0.0f;

    for (int kb = 0; kb < Kt; kb += BK) {
#pragma unroll
        for (int i = tid * 4; i < BM * BK; i += THREADS * 4) {
            int r = i / BK, c = i % BK;
            float4 v = *reinterpret_cast<const float4*>(A + (size_t)(bm + r) * lda + kb + c);
            As[c + 0][r] = v.x; As[c + 1][r] = v.y;
            As[c + 2][r] = v.z; As[c + 3][r] = v.w;
        }
#pragma unroll
        for (int i = tid * 4; i < BN * BK; i += THREADS * 4) {
            int r = i / BK, c = i % BK;
            float4 v = *reinterpret_cast<const float4*>(B + (size_t)(bn + r) * ldb + kb + c);
            Bs[c + 0][r] = v.x; Bs[c + 1][r] = v.y;
            Bs[c + 2][r] = v.z; Bs[c + 3][r] = v.w;
        }
        __syncthreads();
#pragma unroll
        for (int kk = 0; kk < BK; kk++) {
            float a[TM], bf[TN];
#pragma unroll
            for (int i = 0; i < TM; i++) a[i] = As[kk][tr * TM + i];
#pragma unroll
            for (int j = 0; j < TN; j++) bf[j] = Bs[kk][tc * TN + j];
#pragma unroll
            for (int i = 0; i < TM; i++)
#pragma unroll
                for (int j = 0; j < TN; j++) acc[i][j] = fmaf(a[i], bf[j], acc[i][j]);
        }
        __syncthreads();
    }
#pragma unroll
    for (int i = 0; i < TM; i++) {
        int m = bm + tr * TM + i;
#pragma unroll
        for (int j = 0; j < TN; j++) {
            int n = bn + tc * TN + j;
            float v = acc[i][j];
            if (EPI == 1) { v += bias[n]; v = softplusf(v); }
            C[(size_t)m * ldc + n] = v;
        }
    }
}

// ---------------- split-K reduction ----------------
__global__ void reduce_xdbl_kernel() {
    int idx = blockIdx.x * blockDim.x + threadIdx.x;
    float s = 0.0f;
#pragma unroll
    for (int z = 0; z < KSPLIT; z++) s += g_xdpart[(size_t)z * CB * CT * XD + idx];
    g_xdbl[idx] = s;
}

// ---------------- causal dwconv + SiLU (tf32-rounded: feeds x_proj A) ------
__global__ void conv_silu_kernel(const float* __restrict__ xz,
                                 const float* __restrict__ cw,
                                 const float* __restrict__ cb) {
    int idx = blockIdx.x * blockDim.x + threadIdx.x;
    int d = idx & (CDI - 1);
    int bt = idx / CDI;
    int t = bt & (CT - 1);
    int b = bt / CT;
    const float* w = cw + d * CDC;
    float acc = cb[d];
#pragma unroll
    for (int j = 0; j < CDC; j++) {
        int tt = t - (CDC - 1) + j;
        if (tt >= 0) acc += w[j] * xz[((size_t)(b * CT + tt)) * (2 * CDI) + d];
    }
    g_xssm[idx] = tf32r(siluf(acc));
}

// ---------------- scan pass A ----------------
__global__ void scan_passA_kernel(const float* __restrict__ A_log) {
    int d = blockIdx.x * blockDim.x + threadIdx.x;
    int chunk = blockIdx.y;
    int b = blockIdx.z;
    float Ar[CNS], h[CNS], P[CNS];
#pragma unroll
    for (int n = 0; n < CNS; n++) {
        Ar[n] = -__expf(A_log[d * CNS + n]);
        h[n] = 0.0f;
        P[n] = 1.0f;
    }
    int t0 = chunk * CCL;
#pragma unroll 4
    for (int j = 0; j < CCL; j++) {
        int t = t0 + j;
        size_t row = (size_t)(b * CT + t);
        float dtv = g_dt[row * CDI + d];
        float xv  = g_xssm[row * CDI + d];
        float dtx = dtv * xv;
        const float* bp = g_xdbl + row * XD + CDTR;
#pragma unroll
        for (int n = 0; n < CNS; n++) {
            float dA = __expf(dtv * Ar[n]);
            h[n] = fmaf(dA, h[n], dtx * bp[n]);
            P[n] *= dA;
        }
    }
    size_t base = (((size_t)(b * CDI + d)) * CCH + chunk) * CNS;
#pragma unroll
    for (int n = 0; n < CNS; n++) { g_hend[base + n] = h[n]; g_prod[base + n] = P[n]; }
}

// ---------------- scan combine ----------------
__global__ void scan_combine_kernel() {
    int idx = blockIdx.x * blockDim.x + threadIdx.x;
    int n = idx & (CNS - 1);
    int bd = idx / CNS;
    size_t base = (size_t)bd * CCH * CNS + n;
    float H = 0.0f;
#pragma unroll 8
    for (int c = 0; c < CCH; c++) {
        g_hstart[base + (size_t)c * CNS] = H;
        H = fmaf(g_prod[base + (size_t)c * CNS], H, g_hend[base + (size_t)c * CNS]);
    }
}

// ---------------- scan pass B (tf32-rounded output: feeds out_proj A) -----
__global__ void scan_passB_kernel(const float* __restrict__ A_log,
                                  const float* __restrict__ Dskip) {
    int d = blockIdx.x * blockDim.x + threadIdx.x;
    int chunk = blockIdx.y;
    int b = blockIdx.z;
    float Ar[CNS], h[CNS];
    size_t hbase = (((size_t)(b * CDI + d)) * CCH + chunk) * CNS;
#pragma unroll
    for (int n = 0; n < CNS; n++) {
        Ar[n] = -__expf(A_log[d * CNS + n]);
        h[n] = g_hstart[hbase + n];
    }
    float dsk = Dskip[d];
    int t0 = chunk * CCL;
#pragma unroll 4
    for (int j = 0; j < CCL; j++) {
        int t = t0 + j;
        size_t row = (size_t)(b * CT + t);
        float dtv = g_dt[row * CDI + d];
        float xv  = g_xssm[row * CDI + d];
        float dtx = dtv * xv;
        const float* bp = g_xdbl + row * XD + CDTR;
        const float* cp = bp + CNS;
        float y = 0.0f;
#pragma unroll
        for (int n = 0; n < CNS; n++) {
            float dA = __expf(dtv * Ar[n]);
            h[n] = fmaf(dA, h[n], dtx * bp[n]);
            y = fmaf(h[n], cp[n], y);
        }
        float zv = g_xz[row * (2 * CDI) + CDI + d];
        g_y[row * CDI + d] = tf32r((y + xv * dsk) * siluf(zv));
    }
}

// ---------------- host launcher ----------------
extern "C" void kernel_launch(void* const* d_in, const int* in_sizes, int n_in,
                              void* d_out, int out_size) {
    const int*   codes     = (const int*)d_in[0];
    const float* embed_w   = (const float*)d_in[1];
    const float* norm_w    = (const float*)d_in[2];
    const float* in_proj_w = (const float*)d_in[3];
    const float* conv_w    = (const float*)d_in[4];
    const float* conv_b    = (const float*)d_in[5];
    const float* x_proj_w  = (const float*)d_in[6];
    const float* dt_proj_w = (const float*)d_in[7];
    const float* dt_proj_b = (const float*)d_in[8];
    const float* A_log     = (const float*)d_in[9];
    const float* D_skip    = (const float*)d_in[10];
    const float* out_proj_w= (const float*)d_in[11];
    const float* head_w    = (const float*)d_in[12];
    float* out = (float*)d_out;

    float *px, *pxn, *pxz, *pxssm, *pxdpart, *pdt, *py, *pxdbl;
    float *piwr, *powr, *phwr, *pxpr;
    cudaGetSymbolAddress((void**)&px, g_x);
    cudaGetSymbolAddress((void**)&pxn, g_xn);
    cudaGetSymbolAddress((void**)&pxz, g_xz);
    cudaGetSymbolAddress((void**)&pxssm, g_xssm);
    cudaGetSymbolAddress((void**)&pxdpart, g_xdpart);
    cudaGetSymbolAddress((void**)&pdt, g_dt);
    cudaGetSymbolAddress((void**)&py, g_y);
    cudaGetSymbolAddress((void**)&pxdbl, g_xdbl);
    cudaGetSymbolAddress((void**)&piwr, g_iwr);
    cudaGetSymbolAddress((void**)&powr, g_owr);
    cudaGetSymbolAddress((void**)&phwr, g_hwr);
    cudaGetSymbolAddress((void**)&pxpr, g_xpr);

    const int M = CB * CT;   // 2048

    // dynamic smem sizes per instantiation
    constexpr int SMEM_NT128 = 3 * (128 * 20 + 128 * 20) * 4;  // 61440
    constexpr int SMEM_NT64  = 3 * (128 * 20 + 64 * 20) * 4;   // 46080
    constexpr int SMEM_NN128 = 3 * (128 * 20 + 16 * 136) * 4;  // 56832

    cudaFuncSetAttribute((const void*)mma3_kernel<128, 0, true, 0>,
                         cudaFuncAttributeMaxDynamicSharedMemorySize, SMEM_NT128);
    cudaFuncSetAttribute((const void*)mma3_kernel<64, 0, true, 1>,
                         cudaFuncAttributeMaxDynamicSharedMemorySize, SMEM_NT64);
    cudaFuncSetAttribute((const void*)mma3_kernel<64, 3, true, 0>,
                         cudaFuncAttributeMaxDynamicSharedMemorySize, SMEM_NT64);
    cudaFuncSetAttribute((const void*)mma3_kernel<128, 0, false, 2>,
                         cudaFuncAttributeMaxDynamicSharedMemorySize, SMEM_NN128);

    // weight tf32 pre-round + embedding
    round_weights_kernel<<<(IW_ELE + 255) / 256, 256>>>(in_proj_w, out_proj_w,
                                                        head_w, x_proj_w);
    embed_kernel<<<(CB * CT * CDM) / 256, 256>>>(codes, embed_w, px);

    for (int l = 0; l < CL; l++) {
        const float* nw  = norm_w    + (size_t)l * CDM;
        const float* cw  = conv_w    + (size_t)l * CDI * CDC;
        const float* cb  = conv_b    + (size_t)l * CDI;
        const float* dpw = dt_proj_w + (size_t)l * CDI * CDTR;
        const float* dpb = dt_proj_b + (size_t)l * CDI;
        const float* al  = A_log     + (size_t)l * CDI * CNS;
        const float* ds  = D_skip    + (size_t)l * CDI;
        const float* iwr = piwr + (size_t)l * 2 * CDI * CDM;
        const float* owr = powr + (size_t)l * CDM * CDI;
        const float* xpr = pxpr + (size_t)l * XD * CDI;

        rmsnorm_kernel<<<M, 256>>>(px, nw, pxn);

        // in_proj (tf32 MMA): 2048x512 @ (2048x512)^T -> 2048x2048
        mma3_kernel<128, 0, true, 0>
            <<<dim3(2 * CDI / 128, M / 128, 1), 256, SMEM_NT128>>>(
                pxn, iwr, pxz, nullptr, M, 2 * CDI, CDM, CDM, CDM, 2 * CDI, nullptr);

        conv_silu_kernel<<<(CB * CT * CDI) / 256, 256>>>(pxz, cw, cb);

        // x_proj (tf32 MMA, split-K=4): 2048x1024 @ (64x1024)^T -> partials
        mma3_kernel<64, 0, true, 1>
            <<<dim3(1, M / 128, KSPLIT), 256, SMEM_NT64>>>(
                pxssm, xpr, pxdpart, nullptr, M, XD, CDI, CDI, CDI, XD, nullptr);
        reduce_xdbl_kernel<<<(CB * CT * XD) / 256, 256>>>();

        // dt = softplus(dt_lr @ dtp_w^T + b)  (fp32, K=32)
        sgemm_kernel<64, 64, 8, 4, 4, 1>
            <<<dim3(CDI / 64, M / 64, 1), 256>>>(
                pxdbl, dpw, pdt, M, CDI, CDTR, XD, CDTR, CDI, dpb);

        // chunked parallel selective scan
        scan_passA_kernel<<<dim3(CDI / 256, CCH, CB), 256>>>(al);
        scan_combine_kernel<<<(CB * CDI * CNS) / 256, 256>>>();
        scan_passB_kernel<<<dim3(CDI / 256, CCH, CB), 256>>>(al, ds);

        // out_proj + residual; also emit tf32-rounded copy for head
        mma3_kernel<64, 3, true, 0>
            <<<dim3(CDM / 64, M / 128, 1), 256, SMEM_NT64>>>(
                py, owr, px, pxn, M, CDM, CDI, CDI, CDI, CDM, px);
    }

    // head (tf32 MMA, NN, batched z = b*CK + k); A = rounded x from out_proj
    mma3_kernel<128, 0, false, 2>
        <<<dim3(CV / 128, CT / 128, CB * CK), 256, SMEM_NN128>>>(
            pxn, phwr, out, nullptr, CT, CV, CDM, CDM, CV, CV, nullptr);

    (void)in_sizes; (void)n_in; (void)out_size;
}